// round 4
// baseline (speedup 1.0000x reference)
#include <cuda_runtime.h>

#define TT       64
#define NN       2048
#define RPB      16                 // rows (post-neurons) owned per CTA
#define NCTA     (NN / RPB)         // 128 CTAs (1 per SM)
#define NTHREADS 512
#define NWARPS   16                 // warp w owns columns [w*128, w*128+128)
#define FULLM    0xffffffffu

// per-CTA release flags, monotonic across graph replays (each launch adds TT-1)
__device__ unsigned g_flag[NCTA];

__device__ __forceinline__ unsigned ld_acq(const unsigned* p) {
    unsigned v;
    asm volatile("ld.acquire.gpu.global.u32 %0, [%1];" : "=r"(v) : "l"(p) : "memory");
    return v;
}

__global__ void __launch_bounds__(NTHREADS, 1)
snn_persistent(const float* __restrict__ exc,
               const float* __restrict__ w_in,
               const float* __restrict__ tpre_in,
               const float* __restrict__ tpost_in,
               float* __restrict__ out)
{
    __shared__ float part[NWARPS * RPB];   // [srcWarp][row]

    const int tid  = threadIdx.x;
    const int warp = tid >> 5;
    const int lane = tid & 31;
    const int bid  = blockIdx.x;
    const int rowBase = bid * RPB;
    const int colBase = warp * 128 + lane * 4;   // global column of this thread

    // flag base: own flag, read before anyone writes it this launch
    const unsigned base = g_flag[bid];

    // ---- prologue: w rows -> registers (the only big DRAM read) ----
    float w[RPB][4];
    #pragma unroll
    for (int r = 0; r < RPB; ++r) {
        const float4 t = *reinterpret_cast<const float4*>(
            w_in + (size_t)(rowBase + r) * NN + colBase);
        w[r][0] = t.x; w[r][1] = t.y; w[r][2] = t.z; w[r][3] = t.w;
    }
    // pre-trace for own 4 columns (register-carried across all steps)
    float4 p = *reinterpret_cast<const float4*>(tpre_in + colBase);
    // post-trace replica for own 16 rows (1 value per lane<16, per warp)
    float q = (lane < RPB) ? tpost_in[rowBase + lane] : 0.0f;
    float v = 0.0f;   // membrane potential (warp0 lanes<16)

    // ---- step 0: z=0 -> i_syn = 0, no weight update ----
    if (warp == 0) {
        if (lane < RPB) {
            const float x = __ldcg(&exc[rowBase + lane]);
            v = __fadd_rn(v, __fmul_rn(0.1f,
                    __fadd_rn(__fadd_rn(-v, 0.0f), x)));
            const float zn = (__fsub_rn(v, 1.0f) > 0.0f) ? 1.0f : 0.0f;
            v = (zn > 0.0f) ? 0.0f : v;
            out[rowBase + lane] = zn;
        }
        __syncwarp();
        __threadfence();
        if (lane == 0) *((volatile unsigned*)&g_flag[bid]) = base + 1u;
    }

    for (int i = 1; i < TT; ++i) {
        // prefetch input current (warp0 only, hidden behind poll+pass)
        float x = 0.0f;
        if (warp == 0 && lane < RPB) x = __ldcg(&exc[i * NN + rowBase + lane]);

        // ---- wait for the 9 producer CTAs this warp depends on ----
        const unsigned target = base + (unsigned)i;
        const unsigned fidx = (lane < 8) ? (unsigned)(warp * 8 + lane) : (unsigned)bid;
        const unsigned* fp = &g_flag[fidx];
        unsigned fv = ld_acq(fp);
        while (__ballot_sync(FULLM, fv >= target) != FULLM) fv = ld_acq(fp);

        // ---- read z_{i-1}: own 4 columns + own 16 rows ----
        const float4 zv = __ldcg(
            reinterpret_cast<const float4*>(out + (size_t)(i - 1) * NN + colBase));
        float zo = 0.0f;
        if (lane < RPB) zo = __ldcg(&out[(size_t)(i - 1) * NN + rowBase + lane]);

        // ---- trace updates (registers), exact reference rounding ----
        p.x = __fadd_rn(p.x, __fmul_rn(0.05f, __fadd_rn(-p.x, zv.x)));
        p.y = __fadd_rn(p.y, __fmul_rn(0.05f, __fadd_rn(-p.y, zv.y)));
        p.z = __fadd_rn(p.z, __fmul_rn(0.05f, __fadd_rn(-p.z, zv.z)));
        p.w = __fadd_rn(p.w, __fmul_rn(0.05f, __fadd_rn(-p.w, zv.w)));
        q   = __fadd_rn(q,   __fmul_rn(0.05f, __fadd_rn(-q,   zo)));

        // sp_j = rn(1e-3 * tp_j)  (== rn(rn(1e-3*z_i) * tp_j) when z_i=1; 0 else)
        const float spx = __fmul_rn(1e-3f, p.x);
        const float spy = __fmul_rn(1e-3f, p.y);
        const float spz = __fmul_rn(1e-3f, p.z);
        const float spw = __fmul_rn(1e-3f, p.w);
        const float b   = __fmul_rn(1e-3f, q);        // lanes<16 hold own-row b
        const unsigned zmask = __ballot_sync(FULLM, (lane < RPB) && (zo != 0.0f));

        // ---- fused pass: w += dw, acc_r = w_new . z (own 4 cols) ----
        float acc[RPB];
        #pragma unroll
        for (int r = 0; r < RPB; ++r) {
            const float br = __shfl_sync(FULLM, b, r);
            const bool  zr = (zmask >> r) & 1u;

            float t1, t2, wn;
            t1 = zr ? spx : 0.0f;  t2 = __fmul_rn(br, zv.x);
            wn = __fadd_rn(w[r][0], __fsub_rn(t1, t2));
            w[r][0] = fmaxf(wn, 0.0f);                 // upper clip provably dead
            t1 = zr ? spy : 0.0f;  t2 = __fmul_rn(br, zv.y);
            wn = __fadd_rn(w[r][1], __fsub_rn(t1, t2));
            w[r][1] = fmaxf(wn, 0.0f);
            t1 = zr ? spz : 0.0f;  t2 = __fmul_rn(br, zv.z);
            wn = __fadd_rn(w[r][2], __fsub_rn(t1, t2));
            w[r][2] = fmaxf(wn, 0.0f);
            t1 = zr ? spw : 0.0f;  t2 = __fmul_rn(br, zv.w);
            wn = __fadd_rn(w[r][3], __fsub_rn(t1, t2));
            w[r][3] = fmaxf(wn, 0.0f);

            float d = w[r][0] * zv.x;
            d = fmaf(w[r][1], zv.y, d);
            d = fmaf(w[r][2], zv.z, d);
            d = fmaf(w[r][3], zv.w, d);
            acc[r] = d;
        }

        // ---- multi-value tree reduction: 16 accs x 32 lanes -> 16 row sums ----
        #pragma unroll
        for (int r = 0; r < 8; ++r) {
            float keep = (lane & 16) ? acc[r + 8] : acc[r];
            float send = (lane & 16) ? acc[r]     : acc[r + 8];
            acc[r] = keep + __shfl_xor_sync(FULLM, send, 16);
        }
        #pragma unroll
        for (int r = 0; r < 4; ++r) {
            float keep = (lane & 8) ? acc[r + 4] : acc[r];
            float send = (lane & 8) ? acc[r]     : acc[r + 4];
            acc[r] = keep + __shfl_xor_sync(FULLM, send, 8);
        }
        #pragma unroll
        for (int r = 0; r < 2; ++r) {
            float keep = (lane & 4) ? acc[r + 2] : acc[r];
            float send = (lane & 4) ? acc[r]     : acc[r + 2];
            acc[r] = keep + __shfl_xor_sync(FULLM, send, 4);
        }
        {
            float keep = (lane & 2) ? acc[1] : acc[0];
            float send = (lane & 2) ? acc[0] : acc[1];
            acc[0] = keep + __shfl_xor_sync(FULLM, send, 2);
        }
        acc[0] += __shfl_xor_sync(FULLM, acc[0], 1);
        if ((lane & 1) == 0) part[warp * RPB + (lane >> 1)] = acc[0];

        // ---- hand part[] to warp0; warps 1-15 roll ahead to next poll ----
        if (i == TT - 1) {
            __syncthreads();
        } else if (warp == 0) {
            asm volatile("bar.sync 1, %0;" :: "n"(NTHREADS) : "memory");
        } else {
            asm volatile("bar.arrive 1, %0;" :: "n"(NTHREADS) : "memory");
        }

        // ---- warp0: neuron update + publish ----
        if (warp == 0) {
            if (lane < RPB) {
                float isyn = 0.0f;
                #pragma unroll
                for (int k = 0; k < NWARPS; ++k) isyn += part[k * RPB + lane];
                v = __fadd_rn(v, __fmul_rn(0.1f,
                        __fadd_rn(__fadd_rn(-v, isyn), x)));
                const float zn = (__fsub_rn(v, 1.0f) > 0.0f) ? 1.0f : 0.0f;
                v = (zn > 0.0f) ? 0.0f : v;
                out[(size_t)i * NN + rowBase + lane] = zn;
            }
            if (i < TT - 1) {
                __syncwarp();
                __threadfence();
                if (lane == 0)
                    *((volatile unsigned*)&g_flag[bid]) = target + 1u;
            }
        }
    }
}

extern "C" void kernel_launch(void* const* d_in, const int* in_sizes, int n_in,
                              void* d_out, int out_size) {
    const float* exc   = (const float*)d_in[0];  // [T, N]
    const float* w     = (const float*)d_in[1];  // [N, N]
    const float* tpre  = (const float*)d_in[2];  // [N]
    const float* tpost = (const float*)d_in[3];  // [N]
    float*       out   = (float*)d_out;          // [T, N]

    snn_persistent<<<NCTA, NTHREADS>>>(exc, w, tpre, tpost, out);
}

// round 5
// speedup vs baseline: 2.6132x; 2.6132x over previous
#include <cuda_runtime.h>

#define TT       64
#define NN       2048
#define RPB      16                 // rows (post-neurons) per CTA
#define NCTA     (NN / RPB)         // 128 CTAs (1 per SM)
#define NTHREADS 512
#define NWARPS   16                 // warp w owns columns [w*128, w*128+128)
#define FULLM    0xffffffffu

// per-CTA flag: (step_count << 16) | 16-bit spike mask. Monotonic count (48b)
// across graph replays; every launch adds exactly 63 to every CTA's count.
__device__ unsigned long long g_flag[NCTA];

__device__ __forceinline__ unsigned long long ldv64(const unsigned long long* a) {
    unsigned long long r;
    asm volatile("ld.volatile.global.u64 %0, [%1];" : "=l"(r) : "l"(a) : "memory");
    return r;
}
__device__ __forceinline__ void stv64(unsigned long long* a, unsigned long long v) {
    asm volatile("st.volatile.global.u64 [%0], %1;" :: "l"(a), "l"(v) : "memory");
}

__global__ void __launch_bounds__(NTHREADS, 1)
snn_persistent(const float* __restrict__ exc,
               const float* __restrict__ w_in,
               const float* __restrict__ tpre_in,
               const float* __restrict__ tpost_in,
               float* __restrict__ out)
{
    __shared__ float    w_s[RPB * NN];        // 128 KB, rows x cols
    __shared__ unsigned zb[2][NCTA];          // spike masks, double buffered
    __shared__ float    part[NWARPS * RPB];   // [srcWarp][row]

    const int tid  = threadIdx.x;
    const int warp = tid >> 5;
    const int lane = tid & 31;
    const int bid  = blockIdx.x;
    const int rowBase = bid * RPB;
    const int colBase = warp * 128 + lane * 4;     // this thread's 4 global cols
    const int colWord = colBase >> 4;              // flag index owning those cols
    const int colSh   = colBase & 15;              // bit offset within that mask

    const unsigned long long base = g_flag[bid] >> 16;   // launch-uniform

    // ---- prologue: own 16 rows of w -> smem (only big DRAM read) ----
    {
        const float4* src = reinterpret_cast<const float4*>(w_in + (size_t)rowBase * NN);
        float4*       dst = reinterpret_cast<float4*>(w_s);
        #pragma unroll
        for (int k = 0; k < RPB * NN / 4 / NTHREADS; ++k)
            dst[tid + k * NTHREADS] = src[tid + k * NTHREADS];
    }
    // register-resident traces: tp for own 4 cols, tpo replica for own 16 rows
    float4 p = *reinterpret_cast<const float4*>(tpre_in + colBase);
    float  q = (lane < RPB) ? tpost_in[rowBase + lane] : 0.0f;
    float  v = 0.0f;                                   // membrane (warp0 lanes<16)
    __syncthreads();

    // ---- step 0: z = 0 -> i_syn = 0, no weight update ----
    if (warp == 0) {
        float zn = 0.0f;
        if (lane < RPB) {
            const float x = __ldcg(&exc[rowBase + lane]);
            v = __fadd_rn(v, __fmul_rn(0.1f, __fadd_rn(__fadd_rn(-v, 0.0f), x)));
            zn = (__fsub_rn(v, 1.0f) > 0.0f) ? 1.0f : 0.0f;
            v = (zn > 0.0f) ? 0.0f : v;
            out[rowBase + lane] = zn;
        }
        const unsigned bits = __ballot_sync(FULLM, zn > 0.0f) & 0xffffu;
        if (lane == 0)
            stv64(&g_flag[bid], ((base + 1ull) << 16) | (unsigned long long)bits);
    }

    for (int i = 1; i < TT; ++i) {
        const int buf = i & 1;

        // prefetch own input current (warp0; overlaps the poll)
        float x = 0.0f;
        if (warp == 0 && lane < RPB) x = __ldcg(&exc[i * NN + rowBase + lane]);

        // ---- poller warp: wait for all 128 CTAs' step-(i-1) flags ----
        if (warp == 1) {
            const unsigned long long tgt = base + (unsigned long long)i;
            unsigned long long f0, f1, f2, f3;
            do {
                f0 = ldv64(&g_flag[lane]);
                f1 = ldv64(&g_flag[lane + 32]);
                f2 = ldv64(&g_flag[lane + 64]);
                f3 = ldv64(&g_flag[lane + 96]);
            } while (__ballot_sync(FULLM,
                        ((f0 >> 16) >= tgt) & ((f1 >> 16) >= tgt) &
                        ((f2 >> 16) >= tgt) & ((f3 >> 16) >= tgt)) != FULLM);
            zb[buf][lane]      = (unsigned)(f0 & 0xffffu);
            zb[buf][lane + 32] = (unsigned)(f1 & 0xffffu);
            zb[buf][lane + 64] = (unsigned)(f2 & 0xffffu);
            zb[buf][lane + 96] = (unsigned)(f3 & 0xffffu);
        }
        asm volatile("bar.sync 2, %0;" :: "n"(NTHREADS) : "memory");   // z_{i-1} ready

        // ---- expand z bits (registers) ----
        const unsigned cw = zb[buf][colWord];     // mask covering own 4 cols
        const unsigned zw = zb[buf][bid];         // own-row mask
        const float z0 = ((cw >> (colSh + 0)) & 1u) ? 1.0f : 0.0f;
        const float z1 = ((cw >> (colSh + 1)) & 1u) ? 1.0f : 0.0f;
        const float z2 = ((cw >> (colSh + 2)) & 1u) ? 1.0f : 0.0f;
        const float z3 = ((cw >> (colSh + 3)) & 1u) ? 1.0f : 0.0f;
        const float zo = (lane < RPB) ? (((zw >> lane) & 1u) ? 1.0f : 0.0f) : 0.0f;

        // ---- trace updates (exact reference rounding) ----
        p.x = __fadd_rn(p.x, __fmul_rn(0.05f, __fadd_rn(-p.x, z0)));
        p.y = __fadd_rn(p.y, __fmul_rn(0.05f, __fadd_rn(-p.y, z1)));
        p.z = __fadd_rn(p.z, __fmul_rn(0.05f, __fadd_rn(-p.z, z2)));
        p.w = __fadd_rn(p.w, __fmul_rn(0.05f, __fadd_rn(-p.w, z3)));
        q   = __fadd_rn(q,   __fmul_rn(0.05f, __fadd_rn(-q,   zo)));

        // sp = rn(1e-3 * tp)  (== rn(rn(1e-3*z)*tp) when z=1; 0 when z=0)
        const float spx = __fmul_rn(1e-3f, p.x);
        const float spy = __fmul_rn(1e-3f, p.y);
        const float spz = __fmul_rn(1e-3f, p.z);
        const float spw = __fmul_rn(1e-3f, p.w);
        const float bq  = __fmul_rn(1e-3f, q);
        float b[RPB];
        #pragma unroll
        for (int r = 0; r < RPB; ++r) b[r] = __shfl_sync(FULLM, bq, r);

        // ---- fused pass: w += dw (clip), acc_r = w_new . z  ----
        float acc[RPB];
        #pragma unroll
        for (int half = 0; half < 2; ++half) {
            float4 wv[8];
            #pragma unroll
            for (int r = 0; r < 8; ++r)
                wv[r] = *reinterpret_cast<float4*>(&w_s[(half * 8 + r) * NN + colBase]);
            #pragma unroll
            for (int r = 0; r < 8; ++r) {
                const int R = half * 8 + r;
                const bool zr = (zw >> R) & 1u;
                float4 w4 = wv[r];
                float t1, wn;
                t1 = zr ? spx : 0.0f;
                wn = __fadd_rn(w4.x, __fsub_rn(t1, __fmul_rn(b[R], z0)));
                w4.x = fmaxf(wn, 0.0f);                 // upper clip provably dead
                t1 = zr ? spy : 0.0f;
                wn = __fadd_rn(w4.y, __fsub_rn(t1, __fmul_rn(b[R], z1)));
                w4.y = fmaxf(wn, 0.0f);
                t1 = zr ? spz : 0.0f;
                wn = __fadd_rn(w4.z, __fsub_rn(t1, __fmul_rn(b[R], z2)));
                w4.z = fmaxf(wn, 0.0f);
                t1 = zr ? spw : 0.0f;
                wn = __fadd_rn(w4.w, __fsub_rn(t1, __fmul_rn(b[R], z3)));
                w4.w = fmaxf(wn, 0.0f);
                *reinterpret_cast<float4*>(&w_s[R * NN + colBase]) = w4;

                float d = w4.x * z0;
                d = fmaf(w4.y, z1, d);
                d = fmaf(w4.z, z2, d);
                d = fmaf(w4.w, z3, d);
                acc[R] = d;
            }
        }

        // ---- multi-value tree reduction: 16 accs x 32 lanes -> 16 row sums ----
        #pragma unroll
        for (int r = 0; r < 8; ++r) {
            float keep = (lane & 16) ? acc[r + 8] : acc[r];
            float send = (lane & 16) ? acc[r]     : acc[r + 8];
            acc[r] = keep + __shfl_xor_sync(FULLM, send, 16);
        }
        #pragma unroll
        for (int r = 0; r < 4; ++r) {
            float keep = (lane & 8) ? acc[r + 4] : acc[r];
            float send = (lane & 8) ? acc[r]     : acc[r + 4];
            acc[r] = keep + __shfl_xor_sync(FULLM, send, 8);
        }
        #pragma unroll
        for (int r = 0; r < 2; ++r) {
            float keep = (lane & 4) ? acc[r + 2] : acc[r];
            float send = (lane & 4) ? acc[r]     : acc[r + 2];
            acc[r] = keep + __shfl_xor_sync(FULLM, send, 4);
        }
        {
            float keep = (lane & 2) ? acc[1] : acc[0];
            float send = (lane & 2) ? acc[0] : acc[1];
            acc[0] = keep + __shfl_xor_sync(FULLM, send, 2);
        }
        acc[0] += __shfl_xor_sync(FULLM, acc[0], 1);
        if ((lane & 1) == 0) part[warp * RPB + (lane >> 1)] = acc[0];

        // ---- hand part[] to warp0; warps 1-15 roll ahead ----
        if (warp == 0) {
            asm volatile("bar.sync 1, %0;" :: "n"(NTHREADS) : "memory");
            float zn = 0.0f;
            if (lane < RPB) {
                float isyn = 0.0f;
                #pragma unroll
                for (int k = 0; k < NWARPS; ++k) isyn += part[k * RPB + lane];
                v = __fadd_rn(v, __fmul_rn(0.1f, __fadd_rn(__fadd_rn(-v, isyn), x)));
                zn = (__fsub_rn(v, 1.0f) > 0.0f) ? 1.0f : 0.0f;
                v = (zn > 0.0f) ? 0.0f : v;
                out[(size_t)i * NN + rowBase + lane] = zn;
            }
            if (i < TT - 1) {
                const unsigned bits = __ballot_sync(FULLM, zn > 0.0f) & 0xffffu;
                if (lane == 0)
                    stv64(&g_flag[bid],
                          ((base + (unsigned long long)(i + 1)) << 16) |
                          (unsigned long long)bits);
            }
        } else {
            asm volatile("bar.arrive 1, %0;" :: "n"(NTHREADS) : "memory");
        }
    }
}

extern "C" void kernel_launch(void* const* d_in, const int* in_sizes, int n_in,
                              void* d_out, int out_size) {
    const float* exc   = (const float*)d_in[0];  // [T, N]
    const float* w     = (const float*)d_in[1];  // [N, N]
    const float* tpre  = (const float*)d_in[2];  // [N]
    const float* tpost = (const float*)d_in[3];  // [N]
    float*       out   = (float*)d_out;          // [T, N]

    snn_persistent<<<NCTA, NTHREADS>>>(exc, w, tpre, tpost, out);
}